// round 2
// baseline (speedup 1.0000x reference)
#include <cuda_runtime.h>
#include <cuda_bf16.h>
#include <cstdint>

// Problem constants
#define B_   8
#define C_   256
#define H_   96
#define W_   96
#define HW_  (H_*W_)          // 9216
#define G_   4
#define CG_  64               // channels per group
#define HO_  192
#define WO_  192
#define NOUT_ 32

// Scratch: per-output-pixel sampling coords (ix, iy), layout [n=b*4+gi][oy][ox]
__device__ float2 g_coords[B_ * G_ * HO_ * WO_];   // 9.4 MB

// Packed f32x2 FMA (Blackwell): d = a*b + c elementwise on packed pairs
#define FMA2(d,a,b,c) asm("fma.rn.f32x2 %0, %1, %2, %3;" : "=l"(d) : "l"(a), "l"(b), "l"(c))

// ---------------------------------------------------------------------------
// Kernel 1: offset head via packed-f32x2 GEMV.
// Each thread = one (b,h,w); accumulators packed over channel pairs (c, c+1),
// so weights come straight from the natural [o][c] layout as b64 halves.
// ---------------------------------------------------------------------------
__global__ __launch_bounds__(192) void dysample_offset_kernel(
    const float* __restrict__ x,
    const float* __restrict__ w_off,
    const float* __restrict__ b_off)
{
    __shared__ __align__(16) float w_sh[NOUT_ * C_];   // 32 KB, natural [o][c]
    __shared__ float b_sh[NOUT_];

    const int tid = threadIdx.y * 96 + threadIdx.x;
    for (int i = tid; i < NOUT_ * C_; i += 192) w_sh[i] = w_off[i];
    if (tid < NOUT_) b_sh[tid] = b_off[tid];
    __syncthreads();

    const int b = blockIdx.y;
    const int h = blockIdx.x * 2 + threadIdx.y;
    const int w = threadIdx.x;

    const float* xp = x + (size_t)b * C_ * HW_ + h * W_ + w;

    unsigned long long acc[NOUT_];
#pragma unroll
    for (int o = 0; o < NOUT_; o++) acc[o] = 0ull;

#pragma unroll 1
    for (int cb = 0; cb < C_; cb += 4) {
        const float x0 = xp[(cb + 0) * HW_];
        const float x1 = xp[(cb + 1) * HW_];
        const float x2 = xp[(cb + 2) * HW_];
        const float x3 = xp[(cb + 3) * HW_];
        unsigned long long p01, p23;
        asm("mov.b64 %0, {%1,%2};" : "=l"(p01) : "f"(x0), "f"(x1));
        asm("mov.b64 %0, {%1,%2};" : "=l"(p23) : "f"(x2), "f"(x3));
#pragma unroll
        for (int o = 0; o < NOUT_; o++) {
            const ulonglong2 wv = *(const ulonglong2*)&w_sh[o * C_ + cb];  // broadcast LDS.128
            FMA2(acc[o], p01, wv.x, acc[o]);
            FMA2(acc[o], p23, wv.y, acc[o]);
        }
    }

    // Unpack halves, finish offsets
    float offv[NOUT_];
#pragma unroll
    for (int o = 0; o < NOUT_; o++) {
        float lo, hi;
        asm("mov.b64 {%0,%1}, %2;" : "=f"(lo), "=f"(hi) : "l"(acc[o]));
        offv[o] = (lo + hi + b_sh[o]) * 0.25f;
    }

    const float wf = (float)w;
    const float hf = (float)h;
#pragma unroll
    for (int gi = 0; gi < G_; gi++) {
#pragma unroll
        for (int sy = 0; sy < 2; sy++) {
#pragma unroll
            for (int sx = 0; sx < 2; sx++) {
                const int idx = gi * 4 + sy * 2 + sx;
                float ix = wf + offv[idx];
                float iy = hf + offv[16 + idx];
                ix = fminf(fmaxf(ix, 0.f), (float)(W_ - 1));
                iy = fminf(fmaxf(iy, 0.f), (float)(H_ - 1));
                const int n  = b * G_ + gi;
                const int oy = 2 * h + sy;
                const int ox = 2 * w + sx;
                g_coords[((size_t)n * HO_ + oy) * WO_ + ox] = make_float2(ix, iy);
            }
        }
    }
}

// ---------------------------------------------------------------------------
// Kernel 2: bilinear gather from a shared-memory input tile.
// Block = (n, 16-output-row stripe, full 192 width), 192 threads, each thread
// one output column (16 pixels). Input tile: 13 rows x 96 (pad stride 97),
// 4 channels per batch. Rare out-of-tile coords fall back to global loads.
// ---------------------------------------------------------------------------
#define TROWS 13
#define TST   97

__global__ __launch_bounds__(192) void dysample_sample_kernel(
    const float* __restrict__ x,
    float* __restrict__ out)
{
    __shared__ float tile[4][TROWS * TST];   // ~20 KB

    const int ox  = threadIdx.x;
    const int oy0 = blockIdx.x * 16;
    const int n   = blockIdx.y;              // 0..31
    const int b   = n >> 2;
    const int gi  = n & 3;

    int r0 = (oy0 >> 1) - 2;
    if (r0 < 0) r0 = 0;
    if (r0 > H_ - TROWS) r0 = H_ - TROWS;    // 83
    const int r1 = r0 + TROWS - 1;

    // Preload coords for this thread's 16 output pixels into registers
    float cxr[16], cyr[16];
    {
        const float2* cp = g_coords + ((size_t)n * HO_ + oy0) * WO_ + ox;
#pragma unroll
        for (int j = 0; j < 16; j++) {
            const float2 c = cp[(size_t)j * WO_];
            cxr[j] = c.x; cyr[j] = c.y;
        }
    }

    const int ch0 = b * C_ + gi * CG_;
    const int tx = ox % 96;
    const int ty = ox / 96;

#pragma unroll 1
    for (int cb = 0; cb < CG_; cb += 4) {
        const float* src = x + (size_t)(ch0 + cb) * HW_ + r0 * W_;
        __syncthreads();   // all reads of previous tile done
#pragma unroll
        for (int cc = 0; cc < 4; cc++) {
#pragma unroll
            for (int r = ty; r < TROWS; r += 2)
                tile[cc][r * TST + tx] = src[(size_t)cc * HW_ + r * W_ + tx];
        }
        __syncthreads();

#pragma unroll
        for (int j = 0; j < 16; j++) {
            const float ixf = cxr[j], iyf = cyr[j];
            const float x0f = floorf(ixf), y0f = floorf(iyf);
            const int xi0 = (int)x0f, yi0 = (int)y0f;
            const float wx = ixf - x0f, wy = iyf - y0f;
            const int dx  = (xi0 < W_ - 1) ? 1 : 0;
            const int yi1 = min(yi0 + 1, H_ - 1);

            const float w00 = (1.f - wy) * (1.f - wx);
            const float w01 = (1.f - wy) * wx;
            const float w10 = wy * (1.f - wx);
            const float w11 = wy * wx;

            float* op = out + ((size_t)ch0 * HO_ + oy0 + j) * WO_ + ox
                            + (size_t)cb * HO_ * WO_;

            if (yi0 >= r0 && yi1 <= r1) {
                const int base = (yi0 - r0) * TST + xi0;
                const int dy   = (yi1 - yi0) * TST;
#pragma unroll
                for (int cc = 0; cc < 4; cc++) {
                    const float v00 = tile[cc][base];
                    const float v01 = tile[cc][base + dx];
                    const float v10 = tile[cc][base + dy];
                    const float v11 = tile[cc][base + dy + dx];
                    float v = w00 * v00;
                    v = fmaf(w01, v01, v);
                    v = fmaf(w10, v10, v);
                    v = fmaf(w11, v11, v);
                    op[(size_t)cc * HO_ * WO_] = v;
                }
            } else {
                const int base = yi0 * W_ + xi0;
                const int dy   = (yi1 - yi0) * W_;
                const float* g = x + (size_t)(ch0 + cb) * HW_;
#pragma unroll
                for (int cc = 0; cc < 4; cc++) {
                    const float v00 = __ldg(g + (size_t)cc * HW_ + base);
                    const float v01 = __ldg(g + (size_t)cc * HW_ + base + dx);
                    const float v10 = __ldg(g + (size_t)cc * HW_ + base + dy);
                    const float v11 = __ldg(g + (size_t)cc * HW_ + base + dy + dx);
                    float v = w00 * v00;
                    v = fmaf(w01, v01, v);
                    v = fmaf(w10, v10, v);
                    v = fmaf(w11, v11, v);
                    op[(size_t)cc * HO_ * WO_] = v;
                }
            }
        }
    }
}

// ---------------------------------------------------------------------------
extern "C" void kernel_launch(void* const* d_in, const int* in_sizes, int n_in,
                              void* d_out, int out_size)
{
    const float* x     = (const float*)d_in[0];
    const float* w_off = (const float*)d_in[1];
    const float* b_off = (const float*)d_in[2];
    float* out = (float*)d_out;

    dysample_offset_kernel<<<dim3(48, B_), dim3(96, 2)>>>(x, w_off, b_off);
    dysample_sample_kernel<<<dim3(12, B_ * G_), dim3(192)>>>(x, out);
}

// round 3
// speedup vs baseline: 1.6905x; 1.6905x over previous
#include <cuda_runtime.h>
#include <cuda_bf16.h>
#include <cstdint>

// Problem constants
#define B_   8
#define C_   256
#define H_   96
#define W_   96
#define HW_  (H_*W_)          // 9216
#define G_   4
#define CG_  64
#define HO_  192
#define WO_  192
#define HOWO_ (HO_*WO_)       // 36864
#define NOUT_ 32

// Scratch coords (ix, iy) per output pixel, layout [n][oy][ox]
__device__ float2 g_coords[B_ * G_ * HO_ * WO_];   // 9.4 MB

// ---------------------------------------------------------------------------
// Kernel 1: offset head (scalar FFMA GEMV, weights broadcast from SMEM,
// branch-free software prefetch of x).
// ---------------------------------------------------------------------------
__global__ __launch_bounds__(192) void dysample_offset_kernel(
    const float* __restrict__ x,
    const float* __restrict__ w_off,
    const float* __restrict__ b_off)
{
    __shared__ __align__(16) float w_sh[NOUT_ * C_];   // 32 KB
    __shared__ float b_sh[NOUT_];

    const int tid = threadIdx.y * 96 + threadIdx.x;
    for (int i = tid; i < NOUT_ * C_; i += 192) w_sh[i] = w_off[i];
    if (tid < NOUT_) b_sh[tid] = b_off[tid];
    __syncthreads();

    const int b = blockIdx.y;
    const int h = blockIdx.x * 2 + threadIdx.y;
    const int w = threadIdx.x;

    const float* xp = x + (size_t)b * C_ * HW_ + h * W_ + w;

    float acc[NOUT_];
#pragma unroll
    for (int o = 0; o < NOUT_; o++) acc[o] = 0.f;

    float cx0 = xp[0 * HW_], cx1 = xp[1 * HW_], cx2 = xp[2 * HW_], cx3 = xp[3 * HW_];

#pragma unroll 1
    for (int cb = 0; cb < C_; cb += 4) {
        const int cn = (cb + 4 < C_) ? (cb + 4) : (C_ - 4);   // branch-free safe prefetch
        const float nx0 = xp[(cn + 0) * HW_];
        const float nx1 = xp[(cn + 1) * HW_];
        const float nx2 = xp[(cn + 2) * HW_];
        const float nx3 = xp[(cn + 3) * HW_];
#pragma unroll
        for (int o = 0; o < NOUT_; o++) {
            const float4 wv = *(const float4*)&w_sh[o * C_ + cb];
            float t = acc[o];
            t = fmaf(cx0, wv.x, t);
            t = fmaf(cx1, wv.y, t);
            t = fmaf(cx2, wv.z, t);
            t = fmaf(cx3, wv.w, t);
            acc[o] = t;
        }
        cx0 = nx0; cx1 = nx1; cx2 = nx2; cx3 = nx3;
    }

    const float wf = (float)w;
    const float hf = (float)h;
#pragma unroll
    for (int gi = 0; gi < G_; gi++) {
#pragma unroll
        for (int sy = 0; sy < 2; sy++) {
#pragma unroll
            for (int sx = 0; sx < 2; sx++) {
                const int idx = gi * 4 + sy * 2 + sx;
                float ix = wf + (acc[idx]      + b_sh[idx])      * 0.25f;
                float iy = hf + (acc[16 + idx] + b_sh[16 + idx]) * 0.25f;
                ix = fminf(fmaxf(ix, 0.f), (float)(W_ - 1));
                iy = fminf(fmaxf(iy, 0.f), (float)(H_ - 1));
                const int n  = b * G_ + gi;
                const int oy = 2 * h + sy;
                const int ox = 2 * w + sx;
                g_coords[((size_t)n * HO_ + oy) * WO_ + ox] = make_float2(ix, iy);
            }
        }
    }
}

// ---------------------------------------------------------------------------
// Kernel 2: bilinear gather from SMEM tile.
// Block = (n, 4 output rows, full 192 width), 256 threads, 3 pixels/thread.
// Tile: 4 input rows x 96 (stride 100), 8 channels per chunk = 12.8 KB.
// ---------------------------------------------------------------------------
#define TR   4
#define TSD  100
#define CCH  8
#define PXPT 3          // pixels per thread (768 px / 256 thr)

__global__ __launch_bounds__(256) void dysample_sample_kernel(
    const float* __restrict__ x,
    float* __restrict__ out)
{
    __shared__ __align__(16) float tile[CCH * TR * TSD];   // 12.8 KB

    const int tid = threadIdx.x;
    const int n   = blockIdx.y;
    const int b   = n >> 2;
    const int gi  = n & 3;
    const int oy0 = blockIdx.x * 4;
    const int h0  = oy0 >> 1;

    int r0 = h0 - 1;
    if (r0 < 0) r0 = 0;
    if (r0 > H_ - TR) r0 = H_ - TR;   // 92

    // Per-pixel state (computed once, reused across all 64 channels)
    float4 wts[PXPT];
    int a00[PXPT], a01[PXPT], a10[PXPT], a11[PXPT];
    int obase[PXPT];
    unsigned fbmask = 0;

#pragma unroll
    for (int k = 0; k < PXPT; k++) {
        const int p   = tid + k * 256;
        const int ox  = p % WO_;
        const int oyr = p / WO_;
        const float2 c = g_coords[((size_t)n * HO_ + oy0 + oyr) * WO_ + ox];
        const float x0f = floorf(c.x), y0f = floorf(c.y);
        const int xi0 = (int)x0f, yi0 = (int)y0f;
        const float wx = c.x - x0f, wy = c.y - y0f;
        const int xi1 = min(xi0 + 1, W_ - 1);
        const int yi1 = min(yi0 + 1, H_ - 1);
        wts[k] = make_float4((1.f - wy) * (1.f - wx), (1.f - wy) * wx,
                             wy * (1.f - wx),         wy * wx);
        const bool intile = (yi0 >= r0) && (yi1 <= r0 + TR - 1);
        if (intile) {
            const int dxc = xi1 - xi0;
            a00[k] = (yi0 - r0) * TSD + xi0;
            a01[k] = a00[k] + dxc;
            a10[k] = (yi1 - r0) * TSD + xi0;
            a11[k] = a10[k] + dxc;
        } else {
            fbmask |= 1u << k;
            a00[k] = yi0 * W_ + xi0;
            a01[k] = yi0 * W_ + xi1;
            a10[k] = yi1 * W_ + xi0;
            a11[k] = yi1 * W_ + xi1;
        }
        obase[k] = (oy0 + oyr) * WO_ + ox;
    }

    const int ch0 = b * C_ + gi * CG_;
    const float* xg = x + (size_t)ch0 * HW_;
    float* og = out + (size_t)ch0 * HOWO_;

#pragma unroll 1
    for (int cb = 0; cb < CG_; cb += CCH) {
        __syncthreads();
        // Load tile: CCH channels x TR rows x 96 cols, as float4
#pragma unroll
        for (int i = tid; i < CCH * TR * 24; i += 256) {
            const int ch  = i / (TR * 24);
            const int rem = i % (TR * 24);
            const int row = rem / 24;
            const int c4  = rem % 24;
            const float4 v = *(const float4*)(xg + (size_t)(cb + ch) * HW_
                                              + (r0 + row) * W_ + c4 * 4);
            *(float4*)&tile[ch * (TR * TSD) + row * TSD + c4 * 4] = v;
        }
        __syncthreads();

#pragma unroll
        for (int k = 0; k < PXPT; k++) {
            const float4 wv = wts[k];
            float* ob = og + (size_t)cb * HOWO_ + obase[k];
            if (!((fbmask >> k) & 1u)) {
                const int i0 = a00[k], i1 = a01[k], i2 = a10[k], i3 = a11[k];
#pragma unroll
                for (int ch = 0; ch < CCH; ch++) {
                    const float* tc = tile + ch * (TR * TSD);
                    float v = wv.x * tc[i0];
                    v = fmaf(wv.y, tc[i1], v);
                    v = fmaf(wv.z, tc[i2], v);
                    v = fmaf(wv.w, tc[i3], v);
                    ob[(size_t)ch * HOWO_] = v;
                }
            } else {
                const int i0 = a00[k], i1 = a01[k], i2 = a10[k], i3 = a11[k];
#pragma unroll
                for (int ch = 0; ch < CCH; ch++) {
                    const float* gc = xg + (size_t)(cb + ch) * HW_;
                    float v = wv.x * __ldg(gc + i0);
                    v = fmaf(wv.y, __ldg(gc + i1), v);
                    v = fmaf(wv.z, __ldg(gc + i2), v);
                    v = fmaf(wv.w, __ldg(gc + i3), v);
                    ob[(size_t)ch * HOWO_] = v;
                }
            }
        }
    }
}

// ---------------------------------------------------------------------------
extern "C" void kernel_launch(void* const* d_in, const int* in_sizes, int n_in,
                              void* d_out, int out_size)
{
    const float* x     = (const float*)d_in[0];
    const float* w_off = (const float*)d_in[1];
    const float* b_off = (const float*)d_in[2];
    float* out = (float*)d_out;

    dysample_offset_kernel<<<dim3(48, B_), dim3(96, 2)>>>(x, w_off, b_off);
    dysample_sample_kernel<<<dim3(48, B_ * G_), dim3(256)>>>(x, out);
}